// round 6
// baseline (speedup 1.0000x reference)
#include <cuda_runtime.h>
#include <cstdint>

#define MAX_SAMPLES 512
#define THREADS 1024
#define PPT 4
#define CHUNK (THREADS * PPT)

// Match XLA's non-contracted, left-associated evaluation:
// ((x*x) + (y*y)) + (z*z), round-to-nearest, NO FMA contraction.
__device__ __forceinline__ int octant_of(float x, float y, float z) {
    float r2 = __fadd_rn(__fadd_rn(__fmul_rn(x, x), __fmul_rn(y, y)), __fmul_rn(z, z));
    if (!(r2 <= 1.0f)) return -1;
    return ((x >= 0.0f) ? 4 : 0) | ((y >= 0.0f) ? 2 : 0) | ((z >= 0.0f) ? 1 : 0);
}

// One block per batch element. Sequential ordered compaction with early exit.
// OUTPUT IS WRITTEN AS FLOAT32 (R5 post-mortem: harness output dtype is f32;
// int32 index bit-patterns read as float are ~0 -> rel_err exactly 1.0).
__global__ __launch_bounds__(THREADS, 1)
void octant_query_kernel(const float* __restrict__ pcs, float* __restrict__ out, int N) {
    const int b    = blockIdx.x;
    const int tid  = threadIdx.x;
    const int lane = tid & 31;
    const int w    = tid >> 5;          // warp id, 0..31

    float* __restrict__ out_b = out + (size_t)b * (8 * MAX_SAMPLES);

    // Fill this batch's output with DEFAULT (-1.0f). 8*512 = 4096 = 4*THREADS.
#pragma unroll
    for (int j = 0; j < 4; j++)
        out_b[j * THREADS + tid] = -1.0f;

    const float* __restrict__ xs = pcs + (size_t)b * 3 * N;
    const float* __restrict__ ys = xs + N;
    const float* __restrict__ zs = ys + N;

    __shared__ int sh_base[8];        // running exclusive base per octant
    __shared__ int warp_cnt[32][9];   // [warp][octant], padded: conflict-free
    __shared__ int warp_pre[32][9];   // exclusive prefix over warps
    __shared__ int sh_tot[8];         // sub-round totals per octant

    if (tid < 8) sh_base[tid] = 0;
    __syncthreads();

    for (int s = 0; s < N; s += CHUNK) {
        // Batched loads for the whole chunk (12 independent LDGs for MLP).
        int oc[PPT];
        {
            float px[PPT], py[PPT], pz[PPT];
#pragma unroll
            for (int q = 0; q < PPT; q++) {
                int i = s + q * THREADS + tid;
                bool ok = (i < N);
                px[q] = ok ? xs[i] : 2.0f;   // (2,2,2) -> outside ball -> o=-1
                py[q] = ok ? ys[i] : 2.0f;
                pz[q] = ok ? zs[i] : 2.0f;
            }
#pragma unroll
            for (int q = 0; q < PPT; q++)
                oc[q] = octant_of(px[q], py[q], pz[q]);
        }

        // 4 ordered sub-rounds of 1024 points each (block order == index order).
#pragma unroll
        for (int q = 0; q < PPT; q++) {
            const int o = oc[q];

            // Per-warp ballot ranking.
            int lane_rank = 0;
            const unsigned lt = (1u << lane) - 1u;
#pragma unroll
            for (int k = 0; k < 8; k++) {
                unsigned bal = __ballot_sync(0xFFFFFFFFu, o == k);
                if (o == k)   lane_rank = __popc(bal & lt);
                if (lane == 0) warp_cnt[w][k] = __popc(bal);
            }
            __syncthreads();                                   // (A)

            // Warps 0..7: octant k=w, shfl-scan counts across the 32 warps.
            if (w < 8) {
                int v   = warp_cnt[lane][w];
                int inc = v;
#pragma unroll
                for (int d = 1; d < 32; d <<= 1) {
                    int nv = __shfl_up_sync(0xFFFFFFFFu, inc, d);
                    if (lane >= d) inc += nv;
                }
                warp_pre[lane][w] = inc - v;                    // exclusive
                if (lane == 31) sh_tot[w] = inc;                // block total
            }
            __syncthreads();                                   // (B)

            // Ordered write (index as FLOAT).
            if (o >= 0) {
                int rank = sh_base[o] + warp_pre[w][o] + lane_rank;
                if (rank < MAX_SAMPLES)
                    out_b[(o << 9) + rank] = (float)(s + q * THREADS + tid);
            }
            __syncthreads();                                   // (C)

            if (tid < 8) sh_base[tid] += sh_tot[tid];
            __syncthreads();                                   // (D)
        }

        // Early exit once every octant is full (uniform decision via shared).
        bool full = true;
#pragma unroll
        for (int k = 0; k < 8; k++) full = full && (sh_base[k] >= MAX_SAMPLES);
        if (full) break;
    }
}

extern "C" void kernel_launch(void* const* d_in, const int* in_sizes, int n_in,
                              void* d_out, int out_size) {
    const float* pcs = (const float*)d_in[0];
    float* out = (float*)d_out;

    int B = out_size / (8 * MAX_SAMPLES);   // expect 16
    if (B < 1) B = 1;
    if (B > 64) B = 64;
    int N = in_sizes[0] / (3 * B);          // expect 200000

    octant_query_kernel<<<B, THREADS>>>(pcs, out, N);
}

// round 7
// speedup vs baseline: 1.7615x; 1.7615x over previous
#include <cuda_runtime.h>
#include <cstdint>

#define MAX_SAMPLES 512
#define TPB 256            // threads per count/write block (8 warps)
#define CHUNK_A 2048       // points per count/write block
#define ROUNDS (CHUNK_A / TPB)   // 8
#define W_PREFIX 32768     // parallel prefix window (≥10 sigma above fill point)
#define MAXB 64
#define MAXK 32
#define T_THREADS 1024     // tail kernel
#define T_PPT 4
#define T_CHUNK (T_THREADS * T_PPT)

__device__ int g_counts[MAXB * MAXK * 8];

// Match XLA's non-contracted, left-associated ((x*x)+(y*y))+(z*z).
__device__ __forceinline__ int octant_of(float x, float y, float z) {
    float r2 = __fadd_rn(__fadd_rn(__fmul_rn(x, x), __fmul_rn(y, y)), __fmul_rn(z, z));
    if (!(r2 <= 1.0f)) return -1;
    return ((x >= 0.0f) ? 4 : 0) | ((y >= 0.0f) ? 2 : 0) | ((z >= 0.0f) ? 1 : 0);
}

// ---------------------------------------------------------------------------
// Pass 1: per-chunk octant histograms over the prefix window + fill out=-1.
// ---------------------------------------------------------------------------
__global__ void count_kernel(const float* __restrict__ pcs, float* __restrict__ out,
                             int N, int bpb, int out_count) {
    const int b = blockIdx.x / bpb;
    const int k = blockIdx.x % bpb;

    // Blanket-fill output with DEFAULT (-1.0f).
    for (int j = blockIdx.x * TPB + threadIdx.x; j < out_count; j += gridDim.x * TPB)
        out[j] = -1.0f;

    const float* __restrict__ xs = pcs + (size_t)b * 3 * N;
    const float* __restrict__ ys = xs + N;
    const float* __restrict__ zs = ys + N;

    const int start = k * CHUNK_A;
    const int end   = min(start + CHUNK_A, N);

    int cnt[8];
#pragma unroll
    for (int q = 0; q < 8; q++) cnt[q] = 0;

    for (int i = start + threadIdx.x; i < end; i += TPB) {
        int o = octant_of(xs[i], ys[i], zs[i]);
#pragma unroll
        for (int q = 0; q < 8; q++) cnt[q] += (o == q);
    }

    __shared__ int sh[8];
    if (threadIdx.x < 8) sh[threadIdx.x] = 0;
    __syncthreads();

    const int lane = threadIdx.x & 31;
#pragma unroll
    for (int q = 0; q < 8; q++) {
        int v = cnt[q];
#pragma unroll
        for (int off = 16; off > 0; off >>= 1)
            v += __shfl_down_sync(0xFFFFFFFFu, v, off);
        if (lane == 0 && v) atomicAdd(&sh[q], v);
    }
    __syncthreads();

    if (threadIdx.x < 8)
        g_counts[((size_t)b * MAXK + k) * 8 + threadIdx.x] = sh[threadIdx.x];
}

// ---------------------------------------------------------------------------
// Pass 2: ordered write within the prefix window. Blocks whose bases are all
// >= MAX_SAMPLES exit without reading any point data.
// ---------------------------------------------------------------------------
__global__ void write_kernel(const float* __restrict__ pcs, float* __restrict__ out,
                             int N, int bpb) {
    const int b = blockIdx.x / bpb;
    const int k = blockIdx.x % bpb;
    const int tid  = threadIdx.x;
    const int lane = tid & 31;
    const int w    = tid >> 5;       // warp 0..7

    __shared__ int sh_base[8];
    __shared__ int wcnt[8][9];
    __shared__ int wpre[8][9];
    __shared__ int sh_tot[8];

    if (tid < 8) {
        int s = 0;
        for (int kk = 0; kk < k; kk++)
            s += g_counts[((size_t)b * MAXK + kk) * 8 + tid];
        sh_base[tid] = s;
    }
    __syncthreads();

    int base[8];
    bool full = true;
#pragma unroll
    for (int q = 0; q < 8; q++) {
        base[q] = sh_base[q];
        full = full && (base[q] >= MAX_SAMPLES);
    }
    if (full) return;   // uniform: no point reads needed

    const float* __restrict__ xs = pcs + (size_t)b * 3 * N;
    const float* __restrict__ ys = xs + N;
    const float* __restrict__ zs = ys + N;
    float* __restrict__ out_b = out + (size_t)b * (8 * MAX_SAMPLES);

    const int start = k * CHUNK_A;

    // Batched loads for the whole chunk (high MLP).
    int oc[ROUNDS];
#pragma unroll
    for (int r = 0; r < ROUNDS; r++) {
        int i = start + r * TPB + tid;
        bool ok = (i < N);
        float x = ok ? xs[i] : 2.0f;
        float y = ok ? ys[i] : 2.0f;
        float z = ok ? zs[i] : 2.0f;
        oc[r] = octant_of(x, y, z);
    }

    const unsigned lt = (1u << lane) - 1u;

#pragma unroll
    for (int r = 0; r < ROUNDS; r++) {
        // Stop once everything is full (uniform: base identical across threads).
        bool done = true;
#pragma unroll
        for (int q = 0; q < 8; q++) done = done && (base[q] >= MAX_SAMPLES);
        if (done) break;

        const int o = oc[r];
        int lane_rank = 0;
#pragma unroll
        for (int q = 0; q < 8; q++) {
            unsigned bal = __ballot_sync(0xFFFFFFFFu, o == q);
            if (o == q)   lane_rank = __popc(bal & lt);
            if (lane == 0) wcnt[w][q] = __popc(bal);
        }
        __syncthreads();                                // (A)

        if (tid < 64) {                                 // 8 warps x 8 octants
            int q  = tid & 7;
            int ww = tid >> 3;
            int s = 0;
            for (int w2 = 0; w2 < ww; w2++) s += wcnt[w2][q];
            wpre[ww][q] = s;
            if (ww == 7) sh_tot[q] = s + wcnt[7][q];
        }
        __syncthreads();                                // (B)

        if (o >= 0) {
            int rank = base[o] + wpre[w][o] + lane_rank;
            if (rank < MAX_SAMPLES)
                out_b[(o << 9) + rank] = (float)(start + r * TPB + tid);
        }
        // Private base update; sh_tot stable until after next round's bar (A).
#pragma unroll
        for (int q = 0; q < 8; q++) base[q] += sh_tot[q];
    }
}

// ---------------------------------------------------------------------------
// Pass 3: sequential tail beyond the prefix window (correctness fallback;
// returns immediately for the benchmark distribution).
// ---------------------------------------------------------------------------
__global__ __launch_bounds__(T_THREADS, 1)
void tail_kernel(const float* __restrict__ pcs, float* __restrict__ out,
                 int N, int bpb, int tail_start) {
    const int b    = blockIdx.x;
    const int tid  = threadIdx.x;
    const int lane = tid & 31;
    const int w    = tid >> 5;

    __shared__ int sh_base[8];
    __shared__ int warp_cnt[32][9];
    __shared__ int warp_pre[32][9];
    __shared__ int sh_tot[8];

    if (tid < 8) {
        int s = 0;
        for (int kk = 0; kk < bpb; kk++)
            s += g_counts[((size_t)b * MAXK + kk) * 8 + tid];
        sh_base[tid] = s;
    }
    __syncthreads();

    {
        bool full = true;
#pragma unroll
        for (int q = 0; q < 8; q++) full = full && (sh_base[q] >= MAX_SAMPLES);
        if (full) return;
    }

    const float* __restrict__ xs = pcs + (size_t)b * 3 * N;
    const float* __restrict__ ys = xs + N;
    const float* __restrict__ zs = ys + N;
    float* __restrict__ out_b = out + (size_t)b * (8 * MAX_SAMPLES);

    for (int s = tail_start; s < N; s += T_CHUNK) {
        int oc[T_PPT];
#pragma unroll
        for (int q = 0; q < T_PPT; q++) {
            int i = s + q * T_THREADS + tid;
            bool ok = (i < N);
            float x = ok ? xs[i] : 2.0f;
            float y = ok ? ys[i] : 2.0f;
            float z = ok ? zs[i] : 2.0f;
            oc[q] = octant_of(x, y, z);
        }

#pragma unroll
        for (int q = 0; q < T_PPT; q++) {
            const int o = oc[q];
            int lane_rank = 0;
            const unsigned lt = (1u << lane) - 1u;
#pragma unroll
            for (int kk = 0; kk < 8; kk++) {
                unsigned bal = __ballot_sync(0xFFFFFFFFu, o == kk);
                if (o == kk)  lane_rank = __popc(bal & lt);
                if (lane == 0) warp_cnt[w][kk] = __popc(bal);
            }
            __syncthreads();

            if (w < 8) {
                int v   = warp_cnt[lane][w];
                int inc = v;
#pragma unroll
                for (int d = 1; d < 32; d <<= 1) {
                    int nv = __shfl_up_sync(0xFFFFFFFFu, inc, d);
                    if (lane >= d) inc += nv;
                }
                warp_pre[lane][w] = inc - v;
                if (lane == 31) sh_tot[w] = inc;
            }
            __syncthreads();

            if (o >= 0) {
                int rank = sh_base[o] + warp_pre[w][o] + lane_rank;
                if (rank < MAX_SAMPLES)
                    out_b[(o << 9) + rank] = (float)(s + q * T_THREADS + tid);
            }
            __syncthreads();

            if (tid < 8) sh_base[tid] += sh_tot[tid];
            __syncthreads();
        }

        bool full = true;
#pragma unroll
        for (int q = 0; q < 8; q++) full = full && (sh_base[q] >= MAX_SAMPLES);
        if (full) break;
    }
}

// ---------------------------------------------------------------------------
extern "C" void kernel_launch(void* const* d_in, const int* in_sizes, int n_in,
                              void* d_out, int out_size) {
    const float* pcs = (const float*)d_in[0];
    float* out = (float*)d_out;

    int B = out_size / (8 * MAX_SAMPLES);   // 16
    if (B < 1) B = 1;
    if (B > MAXB) B = MAXB;
    int N = in_sizes[0] / (3 * B);          // 200000

    int W = W_PREFIX < N ? W_PREFIX : N;
    int bpb = (W + CHUNK_A - 1) / CHUNK_A;  // <= 16
    if (bpb > MAXK) bpb = MAXK;
    int tail_start = bpb * CHUNK_A;

    dim3 grid(B * bpb);
    count_kernel<<<grid, TPB>>>(pcs, out, N, bpb, B * 8 * MAX_SAMPLES);
    write_kernel<<<grid, TPB>>>(pcs, out, N, bpb);
    tail_kernel<<<B, T_THREADS>>>(pcs, out, N, bpb, tail_start);
}